// round 8
// baseline (speedup 1.0000x reference)
#include <cuda_runtime.h>
#include <cuda_bf16.h>
#include <cstdint>

#define N_ATOMS 50000
#define N_PAIRS 1600000
#define F 128
#define NRBF 20
#define LOG2C 0.69314718055994531f

typedef unsigned long long u64;
typedef unsigned int u32;

// Scratch (allocation-free rule: __device__ globals)
__device__ __align__(16) float g_h[(size_t)N_ATOMS * F];
__device__ __align__(16) float g_agg[(size_t)N_ATOMS * F];
__device__ __align__(16) float g_u[(size_t)N_ATOMS * F];

// ---------------------------------------------------------------------------
// helpers
// ---------------------------------------------------------------------------
__device__ __forceinline__ u32 smem_u32_of(const void* p) {
    u32 a; asm("{ .reg .u64 t; cvta.to.shared.u64 t, %1; cvt.u32.u64 %0, t; }"
               : "=r"(a) : "l"(p));
    return a;
}
__device__ __forceinline__ u64 pk2(float lo, float hi) {
    u64 r; asm("mov.b64 %0,{%1,%2};" : "=l"(r) : "f"(lo), "f"(hi)); return r;
}
__device__ __forceinline__ void upk2(u64 v, float& lo, float& hi) {
    asm("mov.b64 {%0,%1},%2;" : "=f"(lo), "=f"(hi) : "l"(v));
}
__device__ __forceinline__ void ffma2(u64& d, u64 a, u64 b) {
    asm("fma.rn.f32x2 %0,%1,%2,%0;" : "+l"(d) : "l"(a), "l"(b));
}
__device__ __forceinline__ float sspf(float x) {
    float r = (x > 20.0f) ? x : __logf(1.0f + __expf(x));
    return r - LOG2C;
}
__device__ __forceinline__ u32 pkbf(float v0, float v1) {
    u32 r; asm("cvt.rn.bf16x2.f32 %0,%1,%2;" : "=r"(r) : "f"(v1), "f"(v0));
    return r;
}
__device__ __forceinline__ void ldsm4(u32& r0, u32& r1, u32& r2, u32& r3, u32 addr) {
    asm volatile("ldmatrix.sync.aligned.m8n8.x4.shared.b16 {%0,%1,%2,%3},[%4];"
                 : "=r"(r0), "=r"(r1), "=r"(r2), "=r"(r3) : "r"(addr));
}
__device__ __forceinline__ void mma16816(float* c, u32 a0, u32 a1, u32 a2, u32 a3,
                                         u32 b0, u32 b1) {
    asm volatile("mma.sync.aligned.m16n8k16.row.col.f32.bf16.bf16.f32 "
                 "{%0,%1,%2,%3},{%4,%5,%6,%7},{%8,%9},{%0,%1,%2,%3};"
                 : "+f"(c[0]), "+f"(c[1]), "+f"(c[2]), "+f"(c[3])
                 : "r"(a0), "r"(a1), "r"(a2), "r"(a3), "r"(b0), "r"(b1));
}

// ---------------------------------------------------------------------------
// Pair kernel smem map (byte offsets from 1024-aligned base)
// ---------------------------------------------------------------------------
#define TPC 5
#define PB_W2T0 0            // Wf2^T hi bf16 swizzled (32768)
#define PB_W2T1 32768        // Wf2^T lo (32768)
#define PB_TBUF 65536        // 2 x { T hi 32768 | T lo 32768 } = 131072
#define PB_W1   196608       // Wf1 fp32 (10240)
#define PB_B1   206848       // 512
#define PB_B2   207360       // 512
#define PB_META 207872       // 2 x { rc 512 | ii 512 | jj 512 } = 3072
#define PB_END  210944
#define PAIR_SMEM_BYTES (PB_END + 1024)

// ---- Phase A pieces (shared by prologue + interleaved mainloop) ----
__device__ __forceinline__ void paA_init(u64* acc, const float* b1s, int c0) {
    #pragma unroll
    for (int j = 0; j < 16; j++) acc[j] = *(const u64*)&b1s[c0 + 2 * j];
}
__device__ __forceinline__ void paA_step(u64* acc, float fk, const float* w1s,
                                         int k, int c0) {
    u64 aa = pk2(fk, fk);
    const ulonglong2* wp = (const ulonglong2*)&w1s[k * F + c0];
    #pragma unroll
    for (int j2 = 0; j2 < 8; j2++) {
        ulonglong2 wv = wp[j2];
        ffma2(acc[2 * j2], aa, wv.x);
        ffma2(acc[2 * j2 + 1], aa, wv.y);
    }
}
__device__ __forceinline__ void paA_finish(char* smc, u32 t0_off, u32 t1_off,
                                           u64* acc, int r, int wgc) {
    const int xr = r & 7;
    #pragma unroll
    for (int q = 0; q < 4; q++) {
        uint4 hq, lq;
        u32* hp = (u32*)&hq; u32* lp = (u32*)&lq;
        #pragma unroll
        for (int j2 = 0; j2 < 4; j2++) {
            float lo, hi; upk2(acc[4 * q + j2], lo, hi);
            float v0 = sspf(lo), v1 = sspf(hi);
            __nv_bfloat16 h0 = __float2bfloat16(v0), h1 = __float2bfloat16(v1);
            float r0 = v0 - __bfloat162float(h0), r1 = v1 - __bfloat162float(h1);
            hp[j2] = ((u32)__bfloat16_as_ushort(h1) << 16) | __bfloat16_as_ushort(h0);
            lp[j2] = pkbf(r0, r1);
        }
        u32 off = (u32)r * 256u + (u32)(((4 * wgc + q) ^ xr) << 4);
        *(uint4*)(smc + t0_off + off) = hq;
        *(uint4*)(smc + t1_off + off) = lq;
    }
}

extern "C" __global__ void __launch_bounds__(512, 1)
pair_mma_kernel(const float* __restrict__ f_ij, const float* __restrict__ rcut,
                const float* __restrict__ Wf1, const float* __restrict__ bf1,
                const float* __restrict__ Wf2, const float* __restrict__ bf2,
                const int* __restrict__ idx_i, const int* __restrict__ idx_j)
{
    extern __shared__ char smraw[];
    const u32 raw = smem_u32_of(smraw);
    const u32 base = (raw + 1023u) & ~1023u;
    char* smc = smraw + (base - raw);

    float* w1s = (float*)(smc + PB_W1);
    float* b1s = (float*)(smc + PB_B1);
    float* b2s = (float*)(smc + PB_B2);

    const int tid  = threadIdx.x;
    const int lane = tid & 31;
    const int w    = tid >> 5;
    const int wgc  = tid >> 7;          // Phase-A col group
    const int r    = tid & 127;         // Phase-A row
    const int c0   = wgc * 32;

    const long tile0 = (long)blockIdx.x * TPC;   // first 128-pair tile of this CTA

    // ---- one-time loads: Wf2^T hi/lo bf16 (swizzled), Wf1, biases ----
    {
        const int n = tid & 127;
        const int xn = n & 7;
        for (int kc = tid >> 7; kc < 16; kc += 4) {
            float v[8];
            #pragma unroll
            for (int j = 0; j < 8; j++) v[j] = Wf2[(kc * 8 + j) * F + n];
            uint4 hq, lq;
            u32* hp = (u32*)&hq; u32* lp = (u32*)&lq;
            #pragma unroll
            for (int j2 = 0; j2 < 4; j2++) {
                float v0 = v[2 * j2], v1 = v[2 * j2 + 1];
                __nv_bfloat16 h0 = __float2bfloat16(v0), h1 = __float2bfloat16(v1);
                float r0 = v0 - __bfloat162float(h0), r1 = v1 - __bfloat162float(h1);
                hp[j2] = ((u32)__bfloat16_as_ushort(h1) << 16) | __bfloat16_as_ushort(h0);
                lp[j2] = pkbf(r0, r1);
            }
            u32 off = (u32)n * 256u + (u32)((kc ^ xn) << 4);
            *(uint4*)(smc + PB_W2T0 + off) = hq;
            *(uint4*)(smc + PB_W2T1 + off) = lq;
        }
        for (int idx = tid; idx < NRBF * F; idx += 512) w1s[idx] = Wf1[idx];
        if (tid < 128) { b1s[tid] = bf1[tid]; b2s[tid] = bf2[tid]; }
        // stage meta(0) into meta buffer 0
        if (tid < 128) {
            long e = tile0 * 128 + tid;
            *(float*)(smc + PB_META + 0)    + tid;  // (no-op expr guard)
            ((float*)(smc + PB_META))[tid]       = rcut[e];
            ((int*)(smc + PB_META + 512))[tid]   = idx_i[e];
            ((int*)(smc + PB_META + 1024))[tid]  = idx_j[e];
        }
    }

    // f rows for tile 0 -> registers (5 x float4 per thread)
    float fr[NRBF];
    {
        const float4* fp = (const float4*)(f_ij + (tile0 * 128 + r) * NRBF);
        #pragma unroll
        for (int q = 0; q < 5; q++) *(float4*)&fr[4 * q] = __ldg(fp + q);
    }
    __syncthreads();   // weights/biases ready

    // ---- prologue: Phase A (tile 0) -> Tbuf0 ----
    {
        u64 acc[16];
        paA_init(acc, b1s, c0);
        #pragma unroll
        for (int k = 0; k < NRBF; k++) paA_step(acc, fr[k], w1s, k, c0);
        paA_finish(smc, PB_TBUF, PB_TBUF + 32768, acc, r, wgc);
    }
    // prefetch f rows for tile 1
    if (TPC > 1) {
        const float4* fp = (const float4*)(f_ij + ((tile0 + 1) * 128 + r) * NRBF);
        #pragma unroll
        for (int q = 0; q < 5; q++) *(float4*)&fr[4 * q] = __ldg(fp + q);
    }
    __syncthreads();   // Tbuf0 + meta0 ready

    // MMA lane invariants
    const int wrow = (w & 3) * 32;
    const int wcol = (w >> 2) * 32;
    const int m8 = lane >> 3, rin = lane & 7;
    const int rA0 = wrow + ((m8 & 1) << 3) + rin;
    const int cA  = m8 >> 1;
    const int xA  = rA0 & 7;
    const int rB0 = wcol + ((m8 >> 1) << 3) + rin;
    const int cB  = m8 & 1;
    const int xB  = rB0 & 7;
    const u32 W0b = base + PB_W2T0, W1b = base + PB_W2T1;
    const int l4 = lane & 3, lr = lane >> 2;

    for (int t = 0; t < TPC; t++) {
        const bool has_next = (t + 1) < TPC;
        const u32 T0b = base + PB_TBUF + (u32)(t & 1) * 65536u;
        const u32 T1b = T0b + 32768u;
        const u32 nT0 = base + PB_TBUF + (u32)((t + 1) & 1) * 65536u;
        char* metac = smc + PB_META + (t & 1) * 1536;
        char* metan = smc + PB_META + ((t + 1) & 1) * 1536;

        // Phase A accumulators for tile t+1 (interleaved below)
        u64 acc[16];
        if (has_next) paA_init(acc, b1s, c0);

        float cfr[2][4][4];
        #pragma unroll
        for (int rt = 0; rt < 2; rt++)
            #pragma unroll
            for (int nt = 0; nt < 4; nt++)
                #pragma unroll
                for (int i = 0; i < 4; i++) cfr[rt][nt][i] = 0.0f;

        // ---- interleaved: HMMA(t) stages + Phase A(t+1) k-chunks ----
        #pragma unroll
        for (int ks = 0; ks < 8; ks++) {
            // Phase A chunk: k in [ks*20/8, (ks+1)*20/8)
            const int k0 = (ks * NRBF) >> 3, k1 = ((ks + 1) * NRBF) >> 3;
            if (has_next) {
                #pragma unroll
                for (int k = k0; k < k1; k++) paA_step(acc, fr[k], w1s, k, c0);
            }
            // HMMA stage
            u32 oA = (u32)rA0 * 256u + (u32)((((ks << 1) + cA) ^ xA) << 4);
            u32 oB = (u32)rB0 * 256u + (u32)((((ks << 1) + cB) ^ xB) << 4);
            u32 ah[8], al[8], bh[8], bl[8];
            ldsm4(ah[0], ah[1], ah[2], ah[3], T0b + oA);
            ldsm4(ah[4], ah[5], ah[6], ah[7], T0b + oA + 4096);
            ldsm4(al[0], al[1], al[2], al[3], T1b + oA);
            ldsm4(al[4], al[5], al[6], al[7], T1b + oA + 4096);
            ldsm4(bh[0], bh[1], bh[2], bh[3], W0b + oB);
            ldsm4(bh[4], bh[5], bh[6], bh[7], W0b + oB + 4096);
            ldsm4(bl[0], bl[1], bl[2], bl[3], W1b + oB);
            ldsm4(bl[4], bl[5], bl[6], bl[7], W1b + oB + 4096);
            #pragma unroll
            for (int rt = 0; rt < 2; rt++) {
                u32* A0 = &ah[4 * rt]; u32* A1 = &al[4 * rt];
                #pragma unroll
                for (int nt = 0; nt < 4; nt++) {
                    u32 B0a = bh[2 * nt], B0b = bh[2 * nt + 1];
                    u32 B1a = bl[2 * nt], B1b = bl[2 * nt + 1];
                    float* cc = cfr[rt][nt];
                    mma16816(cc, A0[0], A0[1], A0[2], A0[3], B0a, B0b);
                    mma16816(cc, A1[0], A1[1], A1[2], A1[3], B0a, B0b);
                    mma16816(cc, A0[0], A0[1], A0[2], A0[3], B1a, B1b);
                }
            }
        }

        // ---- Phase A(t+1) finish: ssp + bf16 split -> Tbuf[(t+1)&1] ----
        if (has_next) {
            paA_finish(smc, nT0 - base, nT0 - base + 32768u, acc, r, wgc);
            // prefetch f rows for tile t+2 (used in next region's Phase A)
            if (t + 2 < TPC) {
                const float4* fp =
                    (const float4*)(f_ij + ((tile0 + t + 2) * 128 + r) * NRBF);
                #pragma unroll
                for (int q = 0; q < 5; q++) *(float4*)&fr[4 * q] = __ldg(fp + q);
            }
            // stage meta(t+1)
            if (tid < 128) {
                long e = (tile0 + t + 1) * 128 + tid;
                ((float*)metan)[tid]        = rcut[e];
                ((int*)(metan + 512))[tid]  = idx_i[e];
                ((int*)(metan + 1024))[tid] = idx_j[e];
            }
        }

        // ---- epilogue(t) from fragments ----
        const float* rcs = (const float*)metac;
        const int* iis = (const int*)(metac + 512);
        const int* jjs = (const int*)(metac + 1024);
        #pragma unroll
        for (int rt = 0; rt < 2; rt++) {
            #pragma unroll
            for (int half = 0; half < 2; half++) {
                int e = wrow + rt * 16 + half * 8 + lr;
                int ai = iis[e], aj = jjs[e];
                float rcv = rcs[e];
                const float* hrow = g_h + (size_t)aj * F;
                float* arow = g_agg + (size_t)ai * F;
                #pragma unroll
                for (int nt = 0; nt < 4; nt++) {
                    int n = wcol + nt * 8 + 2 * l4;
                    float d0 = cfr[rt][nt][half * 2 + 0];
                    float d1 = cfr[rt][nt][half * 2 + 1];
                    float2 hv = *(const float2*)&hrow[n];
                    float x0 = (d0 + b2s[n]) * rcv * hv.x;
                    float x1 = (d1 + b2s[n + 1]) * rcv * hv.y;
                    asm volatile("red.global.add.v2.f32 [%0], {%1,%2};"
                                 :: "l"(arow + n), "f"(x0), "f"(x1) : "memory");
                }
            }
        }

        __syncthreads();   // region boundary: Tbuf/meta handoff
    }
}

// ---------------------------------------------------------------------------
// Generic 128-wide GEMM (unchanged, passing since R2)
// ---------------------------------------------------------------------------
#define GSM_AT 0
#define GSM_W (128 * 130)
#define GSM_B (GSM_W + 128 * 128)
#define GSM_FLOATS (GSM_B + 128)

extern "C" __global__ void __launch_bounds__(512)
gemm128(const float* __restrict__ A, const float* __restrict__ W,
        const float* __restrict__ bias, float* __restrict__ out,
        int nrows, int mode)
{
    extern __shared__ float sm[];
    float* at = sm + GSM_AT;
    float* ws = sm + GSM_W;
    float* bs = sm + GSM_B;

    const int tid = threadIdx.x;
    const long r0 = (long)blockIdx.x * 128;

    for (int i = tid; i < F * F; i += 512) {
        int r = i >> 7, k = i & 127;
        float v = (r0 + r < nrows) ? A[(r0 + r) * F + k] : 0.0f;
        at[k * 130 + r] = v;
    }
    for (int i = tid; i < F * F; i += 512) ws[i] = W[i];
    if (tid < 128) bs[tid] = bias[tid];
    __syncthreads();

    const int ct = tid & 31, rt = tid >> 5;
    const int R0 = rt << 3, C0 = ct << 2;

    u64 c2[4][4];
    #pragma unroll
    for (int ip = 0; ip < 4; ip++)
        #pragma unroll
        for (int j = 0; j < 4; j++) c2[ip][j] = 0ull;

    #pragma unroll 4
    for (int k = 0; k < F; k++) {
        u64 a[4];
        #pragma unroll
        for (int ip = 0; ip < 4; ip++)
            a[ip] = *(const u64*)&at[k * 130 + R0 + 2 * ip];
        float4 b = *(const float4*)&ws[k * 128 + C0];
        u64 bs0 = pk2(b.x, b.x), bs1 = pk2(b.y, b.y);
        u64 bs2 = pk2(b.z, b.z), bs3 = pk2(b.w, b.w);
        #pragma unroll
        for (int ip = 0; ip < 4; ip++) {
            ffma2(c2[ip][0], a[ip], bs0);
            ffma2(c2[ip][1], a[ip], bs1);
            ffma2(c2[ip][2], a[ip], bs2);
            ffma2(c2[ip][3], a[ip], bs3);
        }
    }

    const float bb0 = bs[C0], bb1 = bs[C0 + 1], bb2v = bs[C0 + 2], bb3 = bs[C0 + 3];
    #pragma unroll
    for (int ip = 0; ip < 4; ip++) {
        float lo[4], hi[4];
        #pragma unroll
        for (int j = 0; j < 4; j++) upk2(c2[ip][j], lo[j], hi[j]);
        long rA = r0 + R0 + 2 * ip;
        if (rA < nrows) {
            float4 o;
            o.x = lo[0] + bb0; o.y = lo[1] + bb1; o.z = lo[2] + bb2v; o.w = lo[3] + bb3;
            if (mode) { o.x = sspf(o.x); o.y = sspf(o.y); o.z = sspf(o.z); o.w = sspf(o.w); }
            *(float4*)&out[rA * F + C0] = o;
        }
        if (rA + 1 < nrows) {
            float4 o;
            o.x = hi[0] + bb0; o.y = hi[1] + bb1; o.z = hi[2] + bb2v; o.w = hi[3] + bb3;
            if (mode) { o.x = sspf(o.x); o.y = sspf(o.y); o.z = sspf(o.z); o.w = sspf(o.w); }
            *(float4*)&out[(rA + 1) * F + C0] = o;
        }
    }
}

extern "C" __global__ void zero_agg_kernel()
{
    long i = (long)blockIdx.x * blockDim.x + threadIdx.x;
    ((float4*)g_agg)[i] = make_float4(0.f, 0.f, 0.f, 0.f);
}

// ---------------------------------------------------------------------------

extern "C" void kernel_launch(void* const* d_in, const int* in_sizes, int n_in,
                              void* d_out, int out_size)
{
    const float* x    = (const float*)d_in[0];
    const float* f_ij = (const float*)d_in[1];
    const float* rcut = (const float*)d_in[2];
    const float* W_in = (const float*)d_in[3];
    const float* b_in = (const float*)d_in[4];
    const float* Wf1  = (const float*)d_in[5];
    const float* bf1  = (const float*)d_in[6];
    const float* Wf2  = (const float*)d_in[7];
    const float* bf2  = (const float*)d_in[8];
    const float* Wo1  = (const float*)d_in[9];
    const float* bo1  = (const float*)d_in[10];
    const float* Wo2  = (const float*)d_in[11];
    const float* bo2  = (const float*)d_in[12];
    const int* idx_i  = (const int*)d_in[13];
    const int* idx_j  = (const int*)d_in[14];
    float* out = (float*)d_out;

    float *h_p = nullptr, *agg_p = nullptr, *u_p = nullptr;
    cudaGetSymbolAddress((void**)&h_p, g_h);
    cudaGetSymbolAddress((void**)&agg_p, g_agg);
    cudaGetSymbolAddress((void**)&u_p, g_u);

    const size_t smP = PAIR_SMEM_BYTES;
    const size_t smG = GSM_FLOATS * sizeof(float);
    cudaFuncSetAttribute((const void*)pair_mma_kernel,
                         cudaFuncAttributeMaxDynamicSharedMemorySize, (int)smP);
    cudaFuncSetAttribute((const void*)gemm128,
                         cudaFuncAttributeMaxDynamicSharedMemorySize, (int)smG);

    const int nblkA = (N_ATOMS + 127) / 128;
    const int nPairBlk = (N_PAIRS / 128) / TPC;   // 2500

    zero_agg_kernel<<<(N_ATOMS * F / 4) / 256, 256>>>();
    gemm128<<<nblkA, 512, smG>>>(x, W_in, b_in, h_p, N_ATOMS, 0);
    pair_mma_kernel<<<nPairBlk, 512, smP>>>(f_ij, rcut, Wf1, bf1, Wf2, bf2, idx_i, idx_j);
    gemm128<<<nblkA, 512, smG>>>(agg_p, Wo1, bo1, u_p, N_ATOMS, 1);
    gemm128<<<nblkA, 512, smG>>>(u_p, Wo2, bo2, out, N_ATOMS, 0);
}

// round 14
// speedup vs baseline: 1.6831x; 1.6831x over previous
#include <cuda_runtime.h>
#include <cuda_bf16.h>
#include <cstdint>

#define N_ATOMS 50000
#define N_PAIRS 1600000
#define F 128
#define NRBF 20
#define LOG2C 0.69314718055994531f

typedef unsigned long long u64;
typedef unsigned int u32;

// Scratch (allocation-free rule: __device__ globals)
__device__ __align__(16) float g_h[(size_t)N_ATOMS * F];
__device__ __align__(16) float g_agg[(size_t)N_ATOMS * F];
__device__ __align__(16) float g_u[(size_t)N_ATOMS * F];

// ---------------------------------------------------------------------------
// helpers
// ---------------------------------------------------------------------------
__device__ __forceinline__ u32 smem_u32_of(const void* p) {
    u32 a; asm("{ .reg .u64 t; cvta.to.shared.u64 t, %1; cvt.u32.u64 %0, t; }"
               : "=r"(a) : "l"(p));
    return a;
}
__device__ __forceinline__ u64 pk2(float lo, float hi) {
    u64 r; asm("mov.b64 %0,{%1,%2};" : "=l"(r) : "f"(lo), "f"(hi)); return r;
}
__device__ __forceinline__ void upk2(u64 v, float& lo, float& hi) {
    asm("mov.b64 {%0,%1},%2;" : "=f"(lo), "=f"(hi) : "l"(v));
}
__device__ __forceinline__ void ffma2(u64& d, u64 a, u64 b) {
    asm("fma.rn.f32x2 %0,%1,%2,%0;" : "+l"(d) : "l"(a), "l"(b));
}
__device__ __forceinline__ float sspf(float x) {
    float r = (x > 20.0f) ? x : __logf(1.0f + __expf(x));
    return r - LOG2C;
}
__device__ __forceinline__ u32 pkbf(float v0, float v1) {
    u32 r; asm("cvt.rn.bf16x2.f32 %0,%1,%2;" : "=r"(r) : "f"(v1), "f"(v0));
    return r;
}
__device__ __forceinline__ void ldsm4(u32& r0, u32& r1, u32& r2, u32& r3, u32 addr) {
    asm volatile("ldmatrix.sync.aligned.m8n8.x4.shared.b16 {%0,%1,%2,%3},[%4];"
                 : "=r"(r0), "=r"(r1), "=r"(r2), "=r"(r3) : "r"(addr));
}
__device__ __forceinline__ void mma16816(float* c, u32 a0, u32 a1, u32 a2, u32 a3,
                                         u32 b0, u32 b1) {
    asm volatile("mma.sync.aligned.m16n8k16.row.col.f32.bf16.bf16.f32 "
                 "{%0,%1,%2,%3},{%4,%5,%6,%7},{%8,%9},{%0,%1,%2,%3};"
                 : "+f"(c[0]), "+f"(c[1]), "+f"(c[2]), "+f"(c[3])
                 : "r"(a0), "r"(a1), "r"(a2), "r"(a3), "r"(b0), "r"(b1));
}

// ---------------------------------------------------------------------------
// Pair kernel: 256 threads/CTA, 2 CTAs/SM, tiles of 64 pairs, TPC tiles/CTA.
// R4-proven phase structure; overlap comes from the co-resident CTA.
// smem map (byte offsets from 1024-aligned base):
// ---------------------------------------------------------------------------
#define TILE 64
#define TPC 10
#define PB_W2T0 0            // Wf2^T hi bf16 swizzled [n=128][k=128] (32768)
#define PB_W2T1 32768        // Wf2^T lo (32768)
#define PB_T0   65536        // T hi [64][128] bf16 swizzled (16384)
#define PB_T1   81920        // T lo (16384)
#define PB_W1   98304        // Wf1 fp32 (10240)
#define PB_B1   108544       // 512
#define PB_B2   109056       // 512
#define PB_RC   109568       // 256
#define PB_II   109824       // 256
#define PB_JJ   110080       // 256
#define PB_END  110336
#define PAIR_SMEM_BYTES (PB_END + 1024)

extern "C" __global__ void __launch_bounds__(256, 2)
pair_mma_kernel(const float* __restrict__ f_ij, const float* __restrict__ rcut,
                const float* __restrict__ Wf1, const float* __restrict__ bf1,
                const float* __restrict__ Wf2, const float* __restrict__ bf2,
                const int* __restrict__ idx_i, const int* __restrict__ idx_j)
{
    extern __shared__ char smraw[];
    const u32 raw = smem_u32_of(smraw);
    const u32 base = (raw + 1023u) & ~1023u;
    char* smc = smraw + (base - raw);

    float* w1s = (float*)(smc + PB_W1);
    float* b1s = (float*)(smc + PB_B1);
    float* b2s = (float*)(smc + PB_B2);
    float* rcs = (float*)(smc + PB_RC);
    int*   iis = (int*)(smc + PB_II);
    int*   jjs = (int*)(smc + PB_JJ);

    const int tid  = threadIdx.x;
    const int lane = tid & 31;
    const int w    = tid >> 5;          // warp 0..7
    const int wgc  = tid >> 6;          // Phase-A col group 0..3
    const int r    = tid & 63;          // Phase-A row / f row
    const int c0   = wgc * 32;

    const long tile0 = (long)blockIdx.x * TPC;

    // ---- one-time: Wf2^T hi/lo bf16 (XOR-swizzled), Wf1, biases ----
    {
        const int n = tid & 127;
        const int xn = n & 7;
        for (int kc = tid >> 7; kc < 16; kc += 2) {
            float v[8];
            #pragma unroll
            for (int j = 0; j < 8; j++) v[j] = Wf2[(kc * 8 + j) * F + n];
            uint4 hq, lq;
            u32* hp = (u32*)&hq; u32* lp = (u32*)&lq;
            #pragma unroll
            for (int j2 = 0; j2 < 4; j2++) {
                float v0 = v[2 * j2], v1 = v[2 * j2 + 1];
                __nv_bfloat16 h0 = __float2bfloat16(v0), h1 = __float2bfloat16(v1);
                float r0 = v0 - __bfloat162float(h0), r1 = v1 - __bfloat162float(h1);
                hp[j2] = ((u32)__bfloat16_as_ushort(h1) << 16) | __bfloat16_as_ushort(h0);
                lp[j2] = pkbf(r0, r1);
            }
            u32 off = (u32)n * 256u + (u32)((kc ^ xn) << 4);
            *(uint4*)(smc + PB_W2T0 + off) = hq;
            *(uint4*)(smc + PB_W2T1 + off) = lq;
        }
        for (int idx = tid; idx < NRBF * F; idx += 256) w1s[idx] = Wf1[idx];
        if (tid < 128) { b1s[tid] = bf1[tid]; b2s[tid] = bf2[tid]; }
    }

    // MMA lane invariants (8 warps: 2 row-groups x 4 col-groups)
    const int wrow = (w & 1) * 32;       // output rows [wrow, wrow+32) of 64
    const int wcol = (w >> 1) * 32;      // output cols [wcol, wcol+32) of 128
    const int m8 = lane >> 3, rin = lane & 7;
    const int rA0 = wrow + ((m8 & 1) << 3) + rin;
    const int cA  = m8 >> 1;
    const int xA  = rA0 & 7;
    const int rB0 = wcol + ((m8 >> 1) << 3) + rin;
    const int cB  = m8 & 1;
    const int xB  = rB0 & 7;
    const u32 T0b = base + PB_T0, T1b = base + PB_T1;
    const u32 W0b = base + PB_W2T0, W1b = base + PB_W2T1;
    const int l4 = lane & 3, lr = lane >> 2;

    for (int t = 0; t < TPC; t++) {
        const long e0 = (tile0 + t) * TILE;

        // f row -> registers (issued before the barrier; latency overlaps it)
        float fr[NRBF];
        {
            const float4* fp = (const float4*)(f_ij + (e0 + r) * NRBF);
            #pragma unroll
            for (int q = 0; q < 5; q++) *(float4*)&fr[4 * q] = __ldg(fp + q);
        }

        __syncthreads();   // prev tile's ldsm/epilogue reads done; smem reusable
        if (tid < TILE) {
            rcs[tid] = rcut[e0 + tid];
            iis[tid] = idx_i[e0 + tid];
            jjs[tid] = idx_j[e0 + tid];
        }

        // ---- Phase A: T = ssp(f @ Wf1 + bf1), split hi/lo bf16 -> smem ----
        {
            u64 acc[16];
            #pragma unroll
            for (int j = 0; j < 16; j++) acc[j] = *(const u64*)&b1s[c0 + 2 * j];
            #pragma unroll
            for (int k = 0; k < NRBF; k++) {
                u64 aa = pk2(fr[k], fr[k]);
                const ulonglong2* wp = (const ulonglong2*)&w1s[k * F + c0];
                #pragma unroll
                for (int j2 = 0; j2 < 8; j2++) {
                    ulonglong2 wv = wp[j2];
                    ffma2(acc[2 * j2], aa, wv.x);
                    ffma2(acc[2 * j2 + 1], aa, wv.y);
                }
            }
            const int xr = r & 7;
            #pragma unroll
            for (int q = 0; q < 4; q++) {
                uint4 hq, lq;
                u32* hp = (u32*)&hq; u32* lp = (u32*)&lq;
                #pragma unroll
                for (int j2 = 0; j2 < 4; j2++) {
                    float lo, hi; upk2(acc[4 * q + j2], lo, hi);
                    float v0 = sspf(lo), v1 = sspf(hi);
                    __nv_bfloat16 h0 = __float2bfloat16(v0), h1 = __float2bfloat16(v1);
                    float r0 = v0 - __bfloat162float(h0), r1 = v1 - __bfloat162float(h1);
                    hp[j2] = ((u32)__bfloat16_as_ushort(h1) << 16) | __bfloat16_as_ushort(h0);
                    lp[j2] = pkbf(r0, r1);
                }
                u32 off = (u32)r * 256u + (u32)(((4 * wgc + q) ^ xr) << 4);
                *(uint4*)(smc + PB_T0 + off) = hq;
                *(uint4*)(smc + PB_T1 + off) = lq;
            }
        }
        __syncthreads();   // T + meta ready

        // ---- Phase B: 3-pass bf16 HMMA; warp owns rows[wrow,+32) x cols[wcol,+32)
        float cfr[2][4][4];
        #pragma unroll
        for (int rt = 0; rt < 2; rt++)
            #pragma unroll
            for (int nt = 0; nt < 4; nt++)
                #pragma unroll
                for (int i = 0; i < 4; i++) cfr[rt][nt][i] = 0.0f;

        #pragma unroll 2
        for (int ks = 0; ks < 8; ks++) {
            u32 oA = (u32)rA0 * 256u + (u32)((((ks << 1) + cA) ^ xA) << 4);
            u32 oB = (u32)rB0 * 256u + (u32)((((ks << 1) + cB) ^ xB) << 4);
            u32 ah[8], al[8], bh[8], bl[8];
            ldsm4(ah[0], ah[1], ah[2], ah[3], T0b + oA);           // rt0 hi
            ldsm4(ah[4], ah[5], ah[6], ah[7], T0b + oA + 4096);    // rt1 hi
            ldsm4(al[0], al[1], al[2], al[3], T1b + oA);           // rt0 lo
            ldsm4(al[4], al[5], al[6], al[7], T1b + oA + 4096);    // rt1 lo
            ldsm4(bh[0], bh[1], bh[2], bh[3], W0b + oB);           // nt0,nt1 hi
            ldsm4(bh[4], bh[5], bh[6], bh[7], W0b + oB + 4096);    // nt2,nt3 hi
            ldsm4(bl[0], bl[1], bl[2], bl[3], W1b + oB);           // nt0,nt1 lo
            ldsm4(bl[4], bl[5], bl[6], bl[7], W1b + oB + 4096);    // nt2,nt3 lo
            #pragma unroll
            for (int rt = 0; rt < 2; rt++) {
                u32* A0 = &ah[4 * rt]; u32* A1 = &al[4 * rt];
                #pragma unroll
                for (int nt = 0; nt < 4; nt++) {
                    u32 B0a = bh[2 * nt], B0b = bh[2 * nt + 1];
                    u32 B1a = bl[2 * nt], B1b = bl[2 * nt + 1];
                    float* cc = cfr[rt][nt];
                    mma16816(cc, A0[0], A0[1], A0[2], A0[3], B0a, B0b); // hi*hi
                    mma16816(cc, A1[0], A1[1], A1[2], A1[3], B0a, B0b); // lo*hi
                    mma16816(cc, A0[0], A0[1], A0[2], A0[3], B1a, B1b); // hi*lo
                }
            }
        }

        // ---- Epilogue from fragment layout ----
        #pragma unroll
        for (int rt = 0; rt < 2; rt++) {
            #pragma unroll
            for (int half = 0; half < 2; half++) {
                int e = wrow + rt * 16 + half * 8 + lr;
                int ai = iis[e], aj = jjs[e];
                float rcv = rcs[e];
                const float* hrow = g_h + (size_t)aj * F;
                float* arow = g_agg + (size_t)ai * F;
                #pragma unroll
                for (int nt = 0; nt < 4; nt++) {
                    int n = wcol + nt * 8 + 2 * l4;
                    float d0 = cfr[rt][nt][half * 2 + 0];
                    float d1 = cfr[rt][nt][half * 2 + 1];
                    float2 hv = *(const float2*)&hrow[n];
                    float x0 = (d0 + b2s[n]) * rcv * hv.x;
                    float x1 = (d1 + b2s[n + 1]) * rcv * hv.y;
                    asm volatile("red.global.add.v2.f32 [%0], {%1,%2};"
                                 :: "l"(arow + n), "f"(x0), "f"(x1) : "memory");
                }
            }
        }
    }
}

// ---------------------------------------------------------------------------
// Generic 128-wide GEMM (unchanged, passing since R2)
// ---------------------------------------------------------------------------
#define GSM_AT 0
#define GSM_W (128 * 130)
#define GSM_B (GSM_W + 128 * 128)
#define GSM_FLOATS (GSM_B + 128)

extern "C" __global__ void __launch_bounds__(512)
gemm128(const float* __restrict__ A, const float* __restrict__ W,
        const float* __restrict__ bias, float* __restrict__ out,
        int nrows, int mode)
{
    extern __shared__ float sm[];
    float* at = sm + GSM_AT;
    float* ws = sm + GSM_W;
    float* bs = sm + GSM_B;

    const int tid = threadIdx.x;
    const long r0 = (long)blockIdx.x * 128;

    for (int i = tid; i < F * F; i += 512) {
        int r = i >> 7, k = i & 127;
        float v = (r0 + r < nrows) ? A[(r0 + r) * F + k] : 0.0f;
        at[k * 130 + r] = v;
    }
    for (int i = tid; i < F * F; i += 512) ws[i] = W[i];
    if (tid < 128) bs[tid] = bias[tid];
    __syncthreads();

    const int ct = tid & 31, rt = tid >> 5;
    const int R0 = rt << 3, C0 = ct << 2;

    u64 c2[4][4];
    #pragma unroll
    for (int ip = 0; ip < 4; ip++)
        #pragma unroll
        for (int j = 0; j < 4; j++) c2[ip][j] = 0ull;

    #pragma unroll 4
    for (int k = 0; k < F; k++) {
        u64 a[4];
        #pragma unroll
        for (int ip = 0; ip < 4; ip++)
            a[ip] = *(const u64*)&at[k * 130 + R0 + 2 * ip];
        float4 b = *(const float4*)&ws[k * 128 + C0];
        u64 bs0 = pk2(b.x, b.x), bs1 = pk2(b.y, b.y);
        u64 bs2 = pk2(b.z, b.z), bs3 = pk2(b.w, b.w);
        #pragma unroll
        for (int ip = 0; ip < 4; ip++) {
            ffma2(c2[ip][0], a[ip], bs0);
            ffma2(c2[ip][1], a[ip], bs1);
            ffma2(c2[ip][2], a[ip], bs2);
            ffma2(c2[ip][3], a[ip], bs3);
        }
    }

    const float bb0 = bs[C0], bb1 = bs[C0 + 1], bb2v = bs[C0 + 2], bb3 = bs[C0 + 3];
    #pragma unroll
    for (int ip = 0; ip < 4; ip++) {
        float lo[4], hi[4];
        #pragma unroll
        for (int j = 0; j < 4; j++) upk2(c2[ip][j], lo[j], hi[j]);
        long rA = r0 + R0 + 2 * ip;
        if (rA < nrows) {
            float4 o;
            o.x = lo[0] + bb0; o.y = lo[1] + bb1; o.z = lo[2] + bb2v; o.w = lo[3] + bb3;
            if (mode) { o.x = sspf(o.x); o.y = sspf(o.y); o.z = sspf(o.z); o.w = sspf(o.w); }
            *(float4*)&out[rA * F + C0] = o;
        }
        if (rA + 1 < nrows) {
            float4 o;
            o.x = hi[0] + bb0; o.y = hi[1] + bb1; o.z = hi[2] + bb2v; o.w = hi[3] + bb3;
            if (mode) { o.x = sspf(o.x); o.y = sspf(o.y); o.z = sspf(o.z); o.w = sspf(o.w); }
            *(float4*)&out[(rA + 1) * F + C0] = o;
        }
    }
}

extern "C" __global__ void zero_agg_kernel()
{
    long i = (long)blockIdx.x * blockDim.x + threadIdx.x;
    ((float4*)g_agg)[i] = make_float4(0.f, 0.f, 0.f, 0.f);
}

// ---------------------------------------------------------------------------

extern "C" void kernel_launch(void* const* d_in, const int* in_sizes, int n_in,
                              void* d_out, int out_size)
{
    const float* x    = (const float*)d_in[0];
    const float* f_ij = (const float*)d_in[1];
    const float* rcut = (const float*)d_in[2];
    const float* W_in = (const float*)d_in[3];
    const float* b_in = (const float*)d_in[4];
    const float* Wf1  = (const float*)d_in[5];
    const float* bf1  = (const float*)d_in[6];
    const float* Wf2  = (const float*)d_in[7];
    const float* bf2  = (const float*)d_in[8];
    const float* Wo1  = (const float*)d_in[9];
    const float* bo1  = (const float*)d_in[10];
    const float* Wo2  = (const float*)d_in[11];
    const float* bo2  = (const float*)d_in[12];
    const int* idx_i  = (const int*)d_in[13];
    const int* idx_j  = (const int*)d_in[14];
    float* out = (float*)d_out;

    float *h_p = nullptr, *agg_p = nullptr, *u_p = nullptr;
    cudaGetSymbolAddress((void**)&h_p, g_h);
    cudaGetSymbolAddress((void**)&agg_p, g_agg);
    cudaGetSymbolAddress((void**)&u_p, g_u);

    const size_t smP = PAIR_SMEM_BYTES;
    const size_t smG = GSM_FLOATS * sizeof(float);
    cudaFuncSetAttribute((const void*)pair_mma_kernel,
                         cudaFuncAttributeMaxDynamicSharedMemorySize, (int)smP);
    cudaFuncSetAttribute((const void*)gemm128,
                         cudaFuncAttributeMaxDynamicSharedMemorySize, (int)smG);

    const int nblkA = (N_ATOMS + 127) / 128;
    const int nPairBlk = (N_PAIRS / TILE) / TPC;   // 25000 / 10 = 2500

    zero_agg_kernel<<<(N_ATOMS * F / 4) / 256, 256>>>();
    gemm128<<<nblkA, 512, smG>>>(x, W_in, b_in, h_p, N_ATOMS, 0);
    pair_mma_kernel<<<nPairBlk, 256, smP>>>(f_ij, rcut, Wf1, bf1, Wf2, bf2, idx_i, idx_j);
    gemm128<<<nblkA, 512, smG>>>(agg_p, Wo1, bo1, u_p, N_ATOMS, 1);
    gemm128<<<nblkA, 512, smG>>>(u_p, Wo2, bo2, out, N_ATOMS, 0);
}